// round 6
// baseline (speedup 1.0000x reference)
#include <cuda_runtime.h>
#include <cstdint>

#define BB 16
#define CC 256
#define HH 64
#define WW 64
#define SSD 512
#define HW 4096

// A chunk image: float2 A2[128 rows][20], col idx = ks*4 + c  ->
//   .x = W[row][ks*8+c], .y = W[row][ks*8+c+4]   (16 used cols, 4 pad)
#define A_CHUNK_F2     2560
#define A_CHUNK_FLOATS 5120
#define A_CHUNK_BYTES  20480

// B buffer: float2 B2[4 ks][4 k2][76 slots]; slot j+1 = image col j;
//   .x = ci ks*8+k2, .y = ci ks*8+k2+4
#define B_BUF_F2   1216
#define B_BUF_FLOATS 2432

// smem float map
#define SM_STY 32
#define SM_A0  288                          // 3 x 5120 floats
#define SM_B0  (288 + 3*A_CHUNK_FLOATS)     // 15648, 2 x 2432
#define SM_FLOATS (SM_B0 + 2*B_BUF_FLOATS)  // 20512
#define SM_BYTES  (SM_FLOATS*4)             // 82048

__device__ float g_inter[BB*CC*HW];
__device__ float g_style[BB*CC];
__device__ float g_demod[BB*CC];
__device__ float g_Rt[CC*CC];
__device__ float g_Wf[9*2*8*A_CHUNK_FLOATS];   // [k][ochalf][cc][A chunk image]

// ---------------- helpers ----------------
__device__ __forceinline__ uint32_t smem_u32(const void* p) {
    uint32_t a;
    asm("{ .reg .u64 t; cvta.to.shared.u64 t, %1; cvt.u32.u64 %0, t; }" : "=r"(a) : "l"(p));
    return a;
}
__device__ __forceinline__ float tf32r(float v) {
    uint32_t r; asm("cvt.rna.tf32.f32 %0, %1;" : "=r"(r) : "f"(v));
    return __uint_as_float(r);
}
__device__ __forceinline__ void mbar_wait(uint32_t mbar, uint32_t parity) {
    asm volatile(
        "{\n\t.reg .pred P;\n\t"
        "WL_%=:\n\t"
        "mbarrier.try_wait.parity.acquire.cta.shared::cta.b64 P, [%0], %1, 0x989680;\n\t"
        "@P bra.uni WD_%=;\n\t"
        "bra.uni WL_%=;\n\t"
        "WD_%=:\n\t}"
        :: "r"(mbar), "r"(parity) : "memory");
}
#define MBAR_INIT(a,n) asm volatile("mbarrier.init.shared.b64 [%0], %1;" :: "r"(a), "r"((uint32_t)(n)) : "memory")

#define MMA_TF32(d, a, b) \
    asm volatile("mma.sync.aligned.m16n8k8.row.col.f32.tf32.tf32.f32 " \
        "{%0,%1,%2,%3}, {%4,%5,%6,%7}, {%8,%9}, {%0,%1,%2,%3};" \
        : "+f"((d)[0]), "+f"((d)[1]), "+f"((d)[2]), "+f"((d)[3]) \
        : "r"((a)[0]), "r"((a)[1]), "r"((a)[2]), "r"((a)[3]), "r"((b)[0]), "r"((b)[1]))

// ---------------- prep kernels ----------------
// style: 4 threads per output channel, shfl-reduced. grid (BB, 4), 256 thr.
__global__ void k_style(const float* __restrict__ wv, const float* __restrict__ sw,
                        const float* __restrict__ sb) {
    __shared__ float s[SSD];
    const int b = blockIdx.x, t = threadIdx.x;
    s[t] = wv[b*SSD + t]; s[t+256] = wv[b*SSD + 256 + t];
    __syncthreads();
    const int ch   = blockIdx.y*64 + (t >> 2);
    const int part = t & 3;
    float acc = 0.f;
    const float* rw = sw + (size_t)ch*SSD + part*128;
    const float* sp = s + part*128;
    #pragma unroll 8
    for (int j = 0; j < 128; j++) acc += sp[j] * rw[j];
    acc += __shfl_xor_sync(0xFFFFFFFF, acc, 1);
    acc += __shfl_xor_sync(0xFFFFFFFF, acc, 2);
    if (part == 0) g_style[b*CC + ch] = acc * 0.03125f + sb[ch];
}

// Rt: grid CC blocks, thread = oc (coalesced writes)
__global__ void k_rt(const float* __restrict__ w) {
    const int ci = blockIdx.x, oc = threadIdx.x;
    const float* src = w + (oc*CC + ci)*9;
    float s2 = 0.f;
    #pragma unroll
    for (int k = 0; k < 9; k++) { float v = src[k]; s2 += v*v; }
    g_Rt[ci*CC + oc] = s2;
}

// Wf: grid (9, 2, 8) = chunk (k, ochalf, cc); 256 threads write 5120 floats
// coalesced; reads gather from w (cached).
__global__ void k_wf(const float* __restrict__ w) {
    const int k = blockIdx.x, oh = blockIdx.y, cc = blockIdx.z;
    float* dst = g_Wf + (size_t)((k*2 + oh)*8 + cc)*A_CHUNK_FLOATS;
    for (int f = threadIdx.x; f < A_CHUNK_FLOATS; f += 256) {
        const int row   = f / 40;            // oc low bits
        const int inrow = f - row*40;
        const int colf2 = inrow >> 1;
        const int half  = inrow & 1;
        const int ks    = colf2 >> 2, c = colf2 & 3;
        float v = 0.f;
        if (colf2 < 16) {
            const int oc = oh*128 + row;
            const int ci = cc*32 + ks*8 + c + 4*half;
            v = tf32r(w[(size_t)(oc*CC + ci)*9 + k]);
        }
        dst[f] = v;
    }
}

// demod: 4 threads per output channel. grid (BB, 4), 256 thr.
__global__ void k_demod() {
    __shared__ float st2[CC];
    const int b = blockIdx.x, t = threadIdx.x;
    float s = g_style[b*CC + t];
    st2[t] = s*s;
    __syncthreads();
    const int ch   = blockIdx.y*64 + (t >> 2);
    const int part = t & 3;
    float acc = 0.f;
    #pragma unroll 8
    for (int i = 0; i < 64; i++) acc += st2[part*64 + i] * g_Rt[(part*64 + i)*CC + ch];
    acc += __shfl_xor_sync(0xFFFFFFFF, acc, 1);
    acc += __shfl_xor_sync(0xFFFFFFFF, acc, 2);
    if (part == 0) g_demod[b*CC + ch] = rsqrtf(acc + 1e-8f);
}

// ---------------- mma.sync tf32 implicit-GEMM conv ----------------
__global__ __launch_bounds__(256, 2)
void k_conv(const float* __restrict__ xg, float* __restrict__ outg,
            const float* __restrict__ noise, const float* __restrict__ nw,
            int stage1) {
    extern __shared__ float sm[];
    const uint32_t base = smem_u32(sm);

    const float* xin  = stage1 ? xg : g_inter;
    float*       outp = stage1 ? g_inter : outg;

    const int tid = threadIdx.x, wid = tid >> 5, lane = tid & 31;
    const int woc = wid & 3;
    const int wn  = wid >> 2;
    const int y   = blockIdx.x;
    const int ocsel = blockIdx.y;
    const int oc0 = ocsel * 128;
    const int b   = blockIdx.z;

    sm[SM_STY + tid] = g_style[b*CC + tid];
    if (tid == 0) { MBAR_INIT(base+0, 1); MBAR_INIT(base+8, 1); MBAR_INIT(base+16, 1); }
    __syncthreads();

#define BULKA(c_) do { \
        int cc_ = (c_)/9, k_ = (c_) - cc_*9; \
        const float* src_ = g_Wf + (size_t)((k_*2 + ocsel)*8 + cc_)*A_CHUNK_FLOATS; \
        uint32_t dst_ = base + (uint32_t)(SM_A0 + ((c_)%3)*A_CHUNK_FLOATS)*4u; \
        uint32_t mb_  = base + (uint32_t)(((c_)%3)*8); \
        asm volatile("mbarrier.arrive.expect_tx.shared.b64 _, [%0], %1;" \
            :: "r"(mb_), "r"((uint32_t)A_CHUNK_BYTES) : "memory"); \
        asm volatile("cp.async.bulk.shared::cluster.global.mbarrier::complete_tx::bytes " \
            "[%0], [%1], %2, [%3];" \
            :: "r"(dst_), "l"(src_), "r"((uint32_t)A_CHUNK_BYTES), "r"(mb_) : "memory"); \
    } while (0)

    // B producer staging
    const int bj = tid >> 3;        // ci row 0..31
    const int bq = tid & 7;         // col octet
    const int bks = bj >> 3, bkk = bj & 7;
    const int bk2 = bkk & 3, bhalf = bkk >> 2;
    const int bbase0 = SM_B0 + (bks*304 + bk2*76)*2 + bhalf;
    float4 bv0, bv1;

#define LOADB(c_) do { \
        int cc_ = (c_)/9, k_ = (c_) - cc_*9, dy_ = k_/3; \
        int gy_ = y + dy_ - 1; \
        bool ok_ = (unsigned)gy_ < (unsigned)HH; \
        const float4* p_ = (const float4*)(xin + (size_t)((b*CC + cc_*32 + bj))*HW + gy_*WW + bq*8); \
        bv0 = ok_ ? p_[0] : make_float4(0.f,0.f,0.f,0.f); \
        bv1 = ok_ ? p_[1] : make_float4(0.f,0.f,0.f,0.f); \
    } while (0)

#define STOREB(pb_, c_) do { \
        int cc_ = (c_)/9; \
        float st_ = sm[SM_STY + cc_*32 + bj]; \
        float* d_ = sm + bbase0 + (pb_)*B_BUF_FLOATS; \
        d_[(bq*8 + 1)*2] = tf32r(bv0.x*st_); \
        d_[(bq*8 + 2)*2] = tf32r(bv0.y*st_); \
        d_[(bq*8 + 3)*2] = tf32r(bv0.z*st_); \
        d_[(bq*8 + 4)*2] = tf32r(bv0.w*st_); \
        d_[(bq*8 + 5)*2] = tf32r(bv1.x*st_); \
        d_[(bq*8 + 6)*2] = tf32r(bv1.y*st_); \
        d_[(bq*8 + 7)*2] = tf32r(bv1.z*st_); \
        d_[(bq*8 + 8)*2] = tf32r(bv1.w*st_); \
        if (bq == 0) { d_[0] = 0.f; d_[65*2] = 0.f; } \
    } while (0)

    float acc[2][4][4];
    #pragma unroll
    for (int m = 0; m < 2; m++)
        #pragma unroll
        for (int n = 0; n < 4; n++)
            #pragma unroll
            for (int i = 0; i < 4; i++) acc[m][n][i] = 0.f;

    const int aoff2 = (woc*32 + (lane >> 2))*20 + (lane & 3);
    const int boff2 = (lane & 3)*76 + wn*32 + (lane >> 2);

#define COMPUTE(s_, bbuf_) do { \
        const float2* A2_ = ((const float2*)sm) + (SM_A0/2) + (s_)*A_CHUNK_F2; \
        const float2* B2_ = ((const float2*)sm) + (SM_B0/2) + (bbuf_)*B_BUF_F2 + (s_); \
        _Pragma("unroll") \
        for (int ks = 0; ks < 4; ks++) { \
            float2 a01_0 = A2_[aoff2 + ks*4]; \
            float2 a23_0 = A2_[aoff2 + 160 + ks*4]; \
            float2 a01_1 = A2_[aoff2 + 320 + ks*4]; \
            float2 a23_1 = A2_[aoff2 + 480 + ks*4]; \
            uint32_t af0_[4] = {__float_as_uint(a01_0.x), __float_as_uint(a23_0.x), \
                                __float_as_uint(a01_0.y), __float_as_uint(a23_0.y)}; \
            uint32_t af1_[4] = {__float_as_uint(a01_1.x), __float_as_uint(a23_1.x), \
                                __float_as_uint(a01_1.y), __float_as_uint(a23_1.y)}; \
            _Pragma("unroll") \
            for (int n = 0; n < 4; n++) { \
                float2 b_ = B2_[boff2 + ks*304 + n*8]; \
                uint32_t bf_[2] = {__float_as_uint(b_.x), __float_as_uint(b_.y)}; \
                MMA_TF32(acc[0][n], af0_, bf_); \
                MMA_TF32(acc[1][n], af1_, bf_); \
            } \
        } \
    } while (0)

    // ---- pipeline: 24 groups of 3 chunks (mb slot, dx, A-buf static per s) ----
    LOADB(0);
    if (tid == 0) { BULKA(0); BULKA(1); }
    int ph0 = 0, ph1 = 0, ph2 = 0;

    #pragma unroll 1
    for (int c3 = 0; c3 < 24; c3++) {
        const int c0 = c3*3;
        const int bbuf = c3 & 1;
        // s = 0
        STOREB(bbuf, c0);
        __syncthreads();
        if (tid == 0) BULKA(c0 + 2);
        mbar_wait(base + 0, ph0); ph0 ^= 1;
        COMPUTE(0, bbuf);
        // s = 1
        __syncthreads();
        if (tid == 0 && c0 + 3 < 72) BULKA(c0 + 3);
        mbar_wait(base + 8, ph1); ph1 ^= 1;
        COMPUTE(1, bbuf);
        // s = 2
        __syncthreads();
        if (tid == 0 && c0 + 4 < 72) BULKA(c0 + 4);
        if (c0 + 3 < 72) LOADB(c0 + 3);
        mbar_wait(base + 16, ph2); ph2 ^= 1;
        COMPUTE(2, bbuf);
    }

#undef BULKA
#undef LOADB
#undef STOREB
#undef COMPUTE

    // ---- epilogue: demod, noise, leaky ReLU ----
    const int r = lane >> 2, tig = lane & 3;
    #pragma unroll
    for (int m = 0; m < 2; m++) {
        const int ocA = oc0 + woc*32 + m*16 + r;
        const int ocB = ocA + 8;
        const float dA = __ldg(&g_demod[b*CC + ocA]);
        const float dB = __ldg(&g_demod[b*CC + ocB]);
        const float nA = __ldg(&nw[ocA]);
        const float nB = __ldg(&nw[ocB]);
        #pragma unroll
        for (int n = 0; n < 4; n++) {
            const int col = wn*32 + n*8 + tig*2;
            const float2 nz = *(const float2*)(noise + (size_t)b*HW + y*WW + col);
            float v0 = acc[m][n][0]*dA + nA*nz.x;
            float v1 = acc[m][n][1]*dA + nA*nz.y;
            float v2 = acc[m][n][2]*dB + nB*nz.x;
            float v3 = acc[m][n][3]*dB + nB*nz.y;
            v0 = v0 > 0.f ? v0 : 0.2f*v0;
            v1 = v1 > 0.f ? v1 : 0.2f*v1;
            v2 = v2 > 0.f ? v2 : 0.2f*v2;
            v3 = v3 > 0.f ? v3 : 0.2f*v3;
            *(float2*)(outp + (size_t)(b*CC + ocA)*HW + y*WW + col) = make_float2(v0, v1);
            *(float2*)(outp + (size_t)(b*CC + ocB)*HW + y*WW + col) = make_float2(v2, v3);
        }
    }
}

// ---------------------------------------------------------------------------
extern "C" void kernel_launch(void* const* d_in, const int* in_sizes, int n_in,
                              void* d_out, int out_size) {
    const float* x   = (const float*)d_in[0];
    const float* w1  = (const float*)d_in[1];
    const float* w2  = (const float*)d_in[2];
    const float* n1  = (const float*)d_in[3];
    const float* n2  = (const float*)d_in[4];
    const float* s1w = (const float*)d_in[5];
    const float* s1b = (const float*)d_in[6];
    const float* c1w = (const float*)d_in[7];
    const float* nw1 = (const float*)d_in[8];
    const float* s2w = (const float*)d_in[9];
    const float* s2b = (const float*)d_in[10];
    const float* c2w = (const float*)d_in[11];
    const float* nw2 = (const float*)d_in[12];
    float* out = (float*)d_out;

    static int configured = 0;
    if (!configured) {
        cudaFuncSetAttribute(k_conv, cudaFuncAttributeMaxDynamicSharedMemorySize, SM_BYTES);
        configured = 1;
    }

    dim3 cgrid(HH, 2, BB);
    dim3 sgrid(BB, 4);
    dim3 wgrid(9, 2, 8);

    k_style<<<sgrid, 256>>>(w1, s1w, s1b);
    k_rt   <<<CC, 256>>>(c1w);
    k_wf   <<<wgrid, 256>>>(c1w);
    k_demod<<<sgrid, 256>>>();
    k_conv <<<cgrid, 256, SM_BYTES>>>(x, out, n1, nw1, 1);

    k_style<<<sgrid, 256>>>(w2, s2w, s2b);
    k_rt   <<<CC, 256>>>(c2w);
    k_wf   <<<wgrid, 256>>>(c2w);
    k_demod<<<sgrid, 256>>>();
    k_conv <<<cgrid, 256, SM_BYTES>>>(x, out, n2, nw2, 0);
}

// round 8
// speedup vs baseline: 1.2441x; 1.2441x over previous
#include <cuda_runtime.h>
#include <cstdint>

#define BB 16
#define CC 256
#define HH 64
#define WW 64
#define SSD 512
#define HW 4096

// A chunk image: [128 oc rows][stride 36] floats (cols 0..31 = ci, 32..35 pad)
#define A_CHUNK_FLOATS 4608
#define A_CHUNK_BYTES  18432

// B buffer: [32 ci][stride 268] ; per ci: 4 rows x stride 67 (slot = col+1; 0/65/66 zero)
#define B_CISTR 268
#define B_ROWSTR 67
#define B_BUF_FLOATS (32*B_CISTR)   // 8576

// smem float map
#define SM_STY 32
#define SM_A0  288
#define SM_B0  (288 + 2*A_CHUNK_FLOATS)          // 9504
#define SM_FLOATS (SM_B0 + 2*B_BUF_FLOATS)       // 26656
#define SM_BYTES  (SM_FLOATS*4)                  // 106624

__device__ float g_inter[BB*CC*HW];
__device__ float g_style[BB*CC];
__device__ float g_demod[BB*CC];
__device__ float g_Rt[CC*CC];
__device__ float g_Wf[9*2*8*A_CHUNK_FLOATS];     // [k][ochalf][cc][A image]

// ---------------- helpers ----------------
__device__ __forceinline__ uint32_t smem_u32(const void* p) {
    uint32_t a;
    asm("{ .reg .u64 t; cvta.to.shared.u64 t, %1; cvt.u32.u64 %0, t; }" : "=r"(a) : "l"(p));
    return a;
}
__device__ __forceinline__ float tf32r(float v) {
    uint32_t r; asm("cvt.rna.tf32.f32 %0, %1;" : "=r"(r) : "f"(v));
    return __uint_as_float(r);
}
__device__ __forceinline__ void mbar_wait(uint32_t mbar, uint32_t parity) {
    asm volatile(
        "{\n\t.reg .pred P;\n\t"
        "WL_%=:\n\t"
        "mbarrier.try_wait.parity.acquire.cta.shared::cta.b64 P, [%0], %1, 0x989680;\n\t"
        "@P bra.uni WD_%=;\n\t"
        "bra.uni WL_%=;\n\t"
        "WD_%=:\n\t}"
        :: "r"(mbar), "r"(parity) : "memory");
}
#define MBAR_INIT(a,n) asm volatile("mbarrier.init.shared.b64 [%0], %1;" :: "r"(a), "r"((uint32_t)(n)) : "memory")

#define MMA_TF32(d, a, b) \
    asm volatile("mma.sync.aligned.m16n8k8.row.col.f32.tf32.tf32.f32 " \
        "{%0,%1,%2,%3}, {%4,%5,%6,%7}, {%8,%9}, {%0,%1,%2,%3};" \
        : "+f"((d)[0]), "+f"((d)[1]), "+f"((d)[2]), "+f"((d)[3]) \
        : "r"((a)[0]), "r"((a)[1]), "r"((a)[2]), "r"((a)[3]), "r"((b)[0]), "r"((b)[1]))

// ---------------- prep kernels ----------------
__global__ void k_style(const float* __restrict__ wv, const float* __restrict__ sw,
                        const float* __restrict__ sb) {
    __shared__ float s[SSD];
    const int b = blockIdx.x, t = threadIdx.x;
    s[t] = wv[b*SSD + t]; s[t+256] = wv[b*SSD + 256 + t];
    __syncthreads();
    const int ch   = blockIdx.y*64 + (t >> 2);
    const int part = t & 3;
    float acc = 0.f;
    const float* rw = sw + (size_t)ch*SSD + part*128;
    const float* sp = s + part*128;
    #pragma unroll 8
    for (int j = 0; j < 128; j++) acc += sp[j] * rw[j];
    acc += __shfl_xor_sync(0xFFFFFFFF, acc, 1);
    acc += __shfl_xor_sync(0xFFFFFFFF, acc, 2);
    if (part == 0) g_style[b*CC + ch] = acc * 0.03125f + sb[ch];
}

__global__ void k_rt(const float* __restrict__ w) {
    const int ci = blockIdx.x, oc = threadIdx.x;
    const float* src = w + (oc*CC + ci)*9;
    float s2 = 0.f;
    #pragma unroll
    for (int k = 0; k < 9; k++) { float v = src[k]; s2 += v*v; }
    g_Rt[ci*CC + oc] = s2;
}

// Wf stride-36 scalar layout: dst[row*36 + j] = tf32(W[oc0+row][cc*32+j][k])
__global__ void k_wf(const float* __restrict__ w) {
    const int k = blockIdx.x, oh = blockIdx.y, cc = blockIdx.z;
    float* dst = g_Wf + (size_t)((k*2 + oh)*8 + cc)*A_CHUNK_FLOATS;
    for (int f = threadIdx.x; f < A_CHUNK_FLOATS; f += 256) {
        const int row = f / 36;
        const int col = f - row*36;
        float v = 0.f;
        if (col < 32)
            v = tf32r(w[(size_t)((oh*128 + row)*CC + cc*32 + col)*9 + k]);
        dst[f] = v;
    }
}

__global__ void k_demod() {
    __shared__ float st2[CC];
    const int b = blockIdx.x, t = threadIdx.x;
    float s = g_style[b*CC + t];
    st2[t] = s*s;
    __syncthreads();
    const int ch   = blockIdx.y*64 + (t >> 2);
    const int part = t & 3;
    float acc = 0.f;
    #pragma unroll 8
    for (int i = 0; i < 64; i++) acc += st2[part*64 + i] * g_Rt[(part*64 + i)*CC + ch];
    acc += __shfl_xor_sync(0xFFFFFFFF, acc, 1);
    acc += __shfl_xor_sync(0xFFFFFFFF, acc, 2);
    if (part == 0) g_demod[b*CC + ch] = rsqrtf(acc + 1e-8f);
}

// ---------------- mma.sync tf32 implicit-GEMM conv ----------------
// CTA: M=128 oc x N=128 px (2 image rows). 8 warps: woc=wid&3 (32 oc),
// wn=wid>>2 (output row). K = 2304 in 72 chunks; A double-buffered bulk-copy,
// B holds 4 input rows per cc, refilled once per cc (producer spread k=0..5).
__global__ __launch_bounds__(256, 2)
void k_conv(const float* __restrict__ xg, float* __restrict__ outg,
            const float* __restrict__ noise, const float* __restrict__ nw,
            int stage1) {
    extern __shared__ float sm[];
    const uint32_t base = smem_u32(sm);

    const float* xin  = stage1 ? xg : g_inter;
    float*       outp = stage1 ? g_inter : outg;

    const int tid = threadIdx.x, wid = tid >> 5, lane = tid & 31;
    const int woc = wid & 3;
    const int wn  = wid >> 2;                // output row within pair
    const int y0  = blockIdx.x * 2;
    const int ocsel = blockIdx.y;
    const int oc0 = ocsel * 128;
    const int b   = blockIdx.z;

    // producer mapping
    const int pci = tid >> 3;                // ci 0..31
    const int pq  = tid & 7;                 // col octet

    // zero B buffers (pads + boundary slots), load styles
    for (int i = tid; i < 2*B_BUF_FLOATS; i += 256) sm[SM_B0 + i] = 0.f;
    sm[SM_STY + tid] = g_style[b*CC + tid];
    if (tid == 0) { MBAR_INIT(base+0, 1); MBAR_INIT(base+8, 1); }
    __syncthreads();

#define LDGROW(r_, ccn_, v0_, v1_) do { \
        int gy_ = y0 - 1 + (r_); \
        if ((unsigned)gy_ < 64u) { \
            const float4* p_ = (const float4*)(xin + \
                (size_t)((b*CC + (ccn_)*32 + pci))*HW + gy_*WW + pq*8); \
            v0_ = p_[0]; v1_ = p_[1]; \
        } else { \
            v0_ = make_float4(0.f,0.f,0.f,0.f); v1_ = make_float4(0.f,0.f,0.f,0.f); \
        } \
    } while (0)

#define STSROW(r_, ccn_, par_, v0_, v1_) do { \
        float st_ = sm[SM_STY + (ccn_)*32 + pci]; \
        float* d_ = sm + SM_B0 + (par_)*B_BUF_FLOATS + pci*B_CISTR + (r_)*B_ROWSTR + 1 + pq*8; \
        d_[0] = tf32r(v0_.x*st_); d_[1] = tf32r(v0_.y*st_); \
        d_[2] = tf32r(v0_.z*st_); d_[3] = tf32r(v0_.w*st_); \
        d_[4] = tf32r(v1_.x*st_); d_[5] = tf32r(v1_.y*st_); \
        d_[6] = tf32r(v1_.z*st_); d_[7] = tf32r(v1_.w*st_); \
    } while (0)

#define BULKA(c_) do { \
        int cc_ = (c_)/9, k_ = (c_) - cc_*9; \
        const float* src_ = g_Wf + (size_t)((k_*2 + ocsel)*8 + cc_)*A_CHUNK_FLOATS; \
        uint32_t dst_ = base + (uint32_t)(SM_A0 + ((c_)&1)*A_CHUNK_FLOATS)*4u; \
        uint32_t mb_  = base + (uint32_t)(((c_)&1)*8); \
        asm volatile("mbarrier.arrive.expect_tx.shared.b64 _, [%0], %1;" \
            :: "r"(mb_), "r"((uint32_t)A_CHUNK_BYTES) : "memory"); \
        asm volatile("cp.async.bulk.shared::cluster.global.mbarrier::complete_tx::bytes " \
            "[%0], [%1], %2, [%3];" \
            :: "r"(dst_), "l"(src_), "r"((uint32_t)A_CHUNK_BYTES), "r"(mb_) : "memory"); \
    } while (0)

    // initial B fill for cc=0 (parity 0)
    {
        float4 t0, t1;
        #pragma unroll
        for (int r = 0; r < 4; r++) { LDGROW(r, 0, t0, t1); STSROW(r, 0, 0, t0, t1); }
    }
    if (tid == 0) { BULKA(0); BULKA(1); }
    __syncthreads();

    float acc[2][8][4];
    #pragma unroll
    for (int m = 0; m < 2; m++)
        #pragma unroll
        for (int n = 0; n < 8; n++)
            #pragma unroll
            for (int i = 0; i < 4; i++) acc[m][n][i] = 0.f;

    const int aidx  = (woc*32 + (lane >> 2))*36 + (lane & 3);
    const int boffk = (lane & 3)*B_CISTR + (lane >> 2);

// slot = image col + 1  ->  input col (xo+dx-1) lives at slot (xo+dx).
// Consumer base therefore adds dx only (NOT 1+dx).
#define COMPUTE(k_, apar_, bpar_) do { \
        const int dy_ = (k_)/3, dx_ = (k_) - dy_*3; \
        const float* A_ = sm + SM_A0 + (apar_)*A_CHUNK_FLOATS + aidx; \
        const float* B_ = sm + SM_B0 + (bpar_)*B_BUF_FLOATS + (wn + dy_)*B_ROWSTR + dx_ + boffk; \
        _Pragma("unroll") \
        for (int ks = 0; ks < 4; ks++) { \
            const float* Ak_ = A_ + ks*8; \
            uint32_t af0_[4] = {__float_as_uint(Ak_[0]),   __float_as_uint(Ak_[288]), \
                                __float_as_uint(Ak_[4]),   __float_as_uint(Ak_[292])}; \
            uint32_t af1_[4] = {__float_as_uint(Ak_[576]), __float_as_uint(Ak_[864]), \
                                __float_as_uint(Ak_[580]), __float_as_uint(Ak_[868])}; \
            const float* Bk_ = B_ + ks*(8*B_CISTR); \
            _Pragma("unroll") \
            for (int nt = 0; nt < 8; nt++) { \
                uint32_t bf_[2] = {__float_as_uint(Bk_[nt*8]), \
                                   __float_as_uint(Bk_[nt*8 + 4*B_CISTR])}; \
                MMA_TF32(acc[0][nt], af0_, bf_); \
                MMA_TF32(acc[1][nt], af1_, bf_); \
            } \
        } \
    } while (0)

    int ph0 = 0, ph1 = 0;
    float4 ra0, ra1, rb0, rb1;   // producer staging (two rows in flight)

    #pragma unroll 1
    for (int cc = 0; cc < 8; cc++) {
        const int par = cc & 1;
        const int npar = par ^ 1;
        const int ccn = cc + 1;
        const bool more = (cc < 7);
        #pragma unroll
        for (int k = 0; k < 9; k++) {
            const int c = cc*9 + k;
            // B producer for next cc, spread across chunks
            if (more) {
                if (k == 0) LDGROW(0, ccn, ra0, ra1);
                if (k == 1) LDGROW(1, ccn, rb0, rb1);
                if (k == 2) { STSROW(0, ccn, npar, ra0, ra1); LDGROW(2, ccn, ra0, ra1); }
                if (k == 3) { STSROW(1, ccn, npar, rb0, rb1); LDGROW(3, ccn, rb0, rb1); }
                if (k == 4) STSROW(2, ccn, npar, ra0, ra1);
                if (k == 5) STSROW(3, ccn, npar, rb0, rb1);
            }
            const int apar = c & 1;
            if (apar == 0) { mbar_wait(base + 0, ph0); ph0 ^= 1; }
            else           { mbar_wait(base + 8, ph1); ph1 ^= 1; }
            COMPUTE(k, apar, par);
            __syncthreads();
            if (tid == 0 && c + 2 < 72) BULKA(c + 2);
        }
    }

#undef LDGROW
#undef STSROW
#undef BULKA
#undef COMPUTE

    // ---- epilogue: demod, noise, leaky ReLU ----
    const int y = y0 + wn;
    const int r = lane >> 2, tig = lane & 3;
    #pragma unroll
    for (int m = 0; m < 2; m++) {
        const int ocA = oc0 + woc*32 + m*16 + r;
        const int ocB = ocA + 8;
        const float dA = __ldg(&g_demod[b*CC + ocA]);
        const float dB = __ldg(&g_demod[b*CC + ocB]);
        const float nA = __ldg(&nw[ocA]);
        const float nB = __ldg(&nw[ocB]);
        #pragma unroll
        for (int nt = 0; nt < 8; nt++) {
            const int col = nt*8 + tig*2;
            const float2 nz = *(const float2*)(noise + (size_t)b*HW + y*WW + col);
            float v0 = acc[m][nt][0]*dA + nA*nz.x;
            float v1 = acc[m][nt][1]*dA + nA*nz.y;
            float v2 = acc[m][nt][2]*dB + nB*nz.x;
            float v3 = acc[m][nt][3]*dB + nB*nz.y;
            v0 = v0 > 0.f ? v0 : 0.2f*v0;
            v1 = v1 > 0.f ? v1 : 0.2f*v1;
            v2 = v2 > 0.f ? v2 : 0.2f*v2;
            v3 = v3 > 0.f ? v3 : 0.2f*v3;
            *(float2*)(outp + (size_t)(b*CC + ocA)*HW + y*WW + col) = make_float2(v0, v1);
            *(float2*)(outp + (size_t)(b*CC + ocB)*HW + y*WW + col) = make_float2(v2, v3);
        }
    }
}

// ---------------------------------------------------------------------------
extern "C" void kernel_launch(void* const* d_in, const int* in_sizes, int n_in,
                              void* d_out, int out_size) {
    const float* x   = (const float*)d_in[0];
    const float* w1  = (const float*)d_in[1];
    const float* w2  = (const float*)d_in[2];
    const float* n1  = (const float*)d_in[3];
    const float* n2  = (const float*)d_in[4];
    const float* s1w = (const float*)d_in[5];
    const float* s1b = (const float*)d_in[6];
    const float* c1w = (const float*)d_in[7];
    const float* nw1 = (const float*)d_in[8];
    const float* s2w = (const float*)d_in[9];
    const float* s2b = (const float*)d_in[10];
    const float* c2w = (const float*)d_in[11];
    const float* nw2 = (const float*)d_in[12];
    float* out = (float*)d_out;

    static int configured = 0;
    if (!configured) {
        cudaFuncSetAttribute(k_conv, cudaFuncAttributeMaxDynamicSharedMemorySize, SM_BYTES);
        configured = 1;
    }

    dim3 cgrid(32, 2, BB);      // 32 row-pairs x 2 oc halves x 16 batches
    dim3 sgrid(BB, 4);
    dim3 wgrid(9, 2, 8);

    k_style<<<sgrid, 256>>>(w1, s1w, s1b);
    k_rt   <<<CC, 256>>>(c1w);
    k_wf   <<<wgrid, 256>>>(c1w);
    k_demod<<<sgrid, 256>>>();
    k_conv <<<cgrid, 256, SM_BYTES>>>(x, out, n1, nw1, 1);

    k_style<<<sgrid, 256>>>(w2, s2w, s2b);
    k_rt   <<<CC, 256>>>(c2w);
    k_wf   <<<wgrid, 256>>>(c2w);
    k_demod<<<sgrid, 256>>>();
    k_conv <<<cgrid, 256, SM_BYTES>>>(x, out, n2, nw2, 0);
}

// round 9
// speedup vs baseline: 2.4519x; 1.9707x over previous
#include <cuda_runtime.h>
#include <cuda_fp16.h>
#include <cstdint>

#define BB 16
#define CC 256
#define HH 64
#define WW 64
#define SSD 512
#define HW 4096

// A chunk image (fp16 pairs): [128 oc rows][20 u32 words]; word j = ci pair (2j,2j+1), j<16; 4 pad
#define A_CHUNK_U32   2560
#define A_CHUNK_BYTES 10240
#define N_ABUF 6

// B buffer (fp16 pairs): [16 k2 words][4 rows][68 slots]; slot = col+2 (0,1,66,67 zero)
#define B_K2STR 280            // 4*68 + 8 pad ; 280 mod 32 = 24 -> conflict-free b-frags
#define B_ROWSTR 68
#define B_BUF_U32 (16*B_K2STR) // 4480

// smem u32 map
#define SM_MB  0               // 6 mbars (8B each)
#define SM_STY 16              // 256 fp32 styles
#define SM_A0  288             // 6 x 2560
#define SM_B0  (288 + N_ABUF*A_CHUNK_U32)   // 15648 ; 2 x 4480
#define SM_U32 (SM_B0 + 2*B_BUF_U32)        // 24608
#define SM_BYTES (SM_U32*4)                 // 98432

__device__ float    g_inter[BB*CC*HW];
__device__ float    g_style[BB*CC];
__device__ float    g_demod[BB*CC];
__device__ float    g_Rt[CC*CC];
__device__ uint32_t g_Wf[9*2*8*A_CHUNK_U32];   // [k][ochalf][cc][A image]

// ---------------- helpers ----------------
__device__ __forceinline__ uint32_t smem_u32(const void* p) {
    uint32_t a;
    asm("{ .reg .u64 t; cvta.to.shared.u64 t, %1; cvt.u32.u64 %0, t; }" : "=r"(a) : "l"(p));
    return a;
}
__device__ __forceinline__ uint32_t packh2(float lo, float hi) {
    __half2 h = __floats2half2_rn(lo, hi);
    return *(uint32_t*)&h;
}
__device__ __forceinline__ void mbar_wait(uint32_t mbar, uint32_t parity) {
    asm volatile(
        "{\n\t.reg .pred P;\n\t"
        "WL_%=:\n\t"
        "mbarrier.try_wait.parity.acquire.cta.shared::cta.b64 P, [%0], %1, 0x989680;\n\t"
        "@P bra.uni WD_%=;\n\t"
        "bra.uni WL_%=;\n\t"
        "WD_%=:\n\t}"
        :: "r"(mbar), "r"(parity) : "memory");
}
#define MBAR_INIT(a,n) asm volatile("mbarrier.init.shared.b64 [%0], %1;" :: "r"(a), "r"((uint32_t)(n)) : "memory")

#define MMA_F16(d, a0,a1,a2,a3, b0,b1) \
    asm volatile("mma.sync.aligned.m16n8k16.row.col.f32.f16.f16.f32 " \
        "{%0,%1,%2,%3}, {%4,%5,%6,%7}, {%8,%9}, {%0,%1,%2,%3};" \
        : "+f"((d)[0]), "+f"((d)[1]), "+f"((d)[2]), "+f"((d)[3]) \
        : "r"(a0), "r"(a1), "r"(a2), "r"(a3), "r"(b0), "r"(b1))

// ---------------- prep kernels ----------------
__global__ void k_style(const float* __restrict__ wv, const float* __restrict__ sw,
                        const float* __restrict__ sb) {
    __shared__ float s[SSD];
    const int b = blockIdx.x, t = threadIdx.x;
    s[t] = wv[b*SSD + t]; s[t+256] = wv[b*SSD + 256 + t];
    __syncthreads();
    const int ch   = blockIdx.y*64 + (t >> 2);
    const int part = t & 3;
    float acc = 0.f;
    const float* rw = sw + (size_t)ch*SSD + part*128;
    const float* sp = s + part*128;
    #pragma unroll 8
    for (int j = 0; j < 128; j++) acc += sp[j] * rw[j];
    acc += __shfl_xor_sync(0xFFFFFFFF, acc, 1);
    acc += __shfl_xor_sync(0xFFFFFFFF, acc, 2);
    if (part == 0) g_style[b*CC + ch] = acc * 0.03125f + sb[ch];
}

__global__ void k_rt(const float* __restrict__ w) {
    const int ci = blockIdx.x, oc = threadIdx.x;
    const float* src = w + (oc*CC + ci)*9;
    float s2 = 0.f;
    #pragma unroll
    for (int k = 0; k < 9; k++) { float v = src[k]; s2 += v*v; }
    g_Rt[ci*CC + oc] = s2;
}

// Wf packed fp16: dst[row*20 + j] = half2(W[oc][2j], W[oc][2j+1]) for j<16, else 0
__global__ void k_wf(const float* __restrict__ w) {
    const int k = blockIdx.x, oh = blockIdx.y, cc = blockIdx.z;
    uint32_t* dst = g_Wf + (size_t)((k*2 + oh)*8 + cc)*A_CHUNK_U32;
    for (int f = threadIdx.x; f < A_CHUNK_U32; f += 256) {
        const int row = f / 20;
        const int j   = f - row*20;
        uint32_t v = 0;
        if (j < 16) {
            const size_t rb = (size_t)((oh*128 + row)*CC + cc*32 + 2*j)*9 + k;
            v = packh2(w[rb], w[rb + 9]);
        }
        dst[f] = v;
    }
}

__global__ void k_demod() {
    __shared__ float st2[CC];
    const int b = blockIdx.x, t = threadIdx.x;
    float s = g_style[b*CC + t];
    st2[t] = s*s;
    __syncthreads();
    const int ch   = blockIdx.y*64 + (t >> 2);
    const int part = t & 3;
    float acc = 0.f;
    #pragma unroll 8
    for (int i = 0; i < 64; i++) acc += st2[part*64 + i] * g_Rt[(part*64 + i)*CC + ch];
    acc += __shfl_xor_sync(0xFFFFFFFF, acc, 1);
    acc += __shfl_xor_sync(0xFFFFFFFF, acc, 2);
    if (part == 0) g_demod[b*CC + ch] = rsqrtf(acc + 1e-8f);
}

// ---------------- fp16 mma.sync implicit-GEMM conv ----------------
// CTA: M=128 oc x N=128 px (2 image rows). 8 warps (woc=wid&3, wn=wid>>2).
// K = 2304 in 72 chunks of 32 ci (2 x m16n8k16). A: 6-deep cp.async.bulk
// pipeline, sync every 3 chunks; B: 4 input rows per cc, double-buffered.
__global__ __launch_bounds__(256, 2)
void k_conv(const float* __restrict__ xg, float* __restrict__ outg,
            const float* __restrict__ noise, const float* __restrict__ nw,
            int stage1) {
    extern __shared__ uint32_t smu[];
    float* smf = (float*)smu;
    const uint32_t base = smem_u32(smu);

    const float* xin  = stage1 ? xg : g_inter;
    float*       outp = stage1 ? g_inter : outg;

    const int tid = threadIdx.x, wid = tid >> 5, lane = tid & 31;
    const int woc = wid & 3;
    const int wn  = wid >> 2;
    const int y0  = blockIdx.x * 2;
    const int ocsel = blockIdx.y;
    const int oc0 = ocsel * 128;
    const int b   = blockIdx.z;

    // producer mapping: ci-pair x px-quad
    const int pcp = tid >> 4;          // ci pair 0..15
    const int ppx = (tid & 15) * 4;    // px 0..60

    for (int i = tid; i < 2*B_BUF_U32; i += 256) smu[SM_B0 + i] = 0;
    smf[SM_STY + tid] = g_style[b*CC + tid];
    if (tid == 0)
        #pragma unroll
        for (int s = 0; s < 6; s++) MBAR_INIT(base + s*8, 1);
    __syncthreads();

#define LDGROW(r_, ccn_, va_, vb_) do { \
        int gy_ = y0 - 1 + (r_); \
        if ((unsigned)gy_ < 64u) { \
            const float* p_ = xin + (size_t)((b*CC + (ccn_)*32 + 2*pcp))*HW + gy_*WW + ppx; \
            va_ = *(const float4*)p_; \
            vb_ = *(const float4*)(p_ + HW); \
        } else { \
            va_ = make_float4(0.f,0.f,0.f,0.f); vb_ = make_float4(0.f,0.f,0.f,0.f); \
        } \
    } while (0)

#define STSROW(r_, ccn_, par_, va_, vb_) do { \
        float s0_ = smf[SM_STY + (ccn_)*32 + 2*pcp]; \
        float s1_ = smf[SM_STY + (ccn_)*32 + 2*pcp + 1]; \
        uint32_t* d_ = smu + SM_B0 + (par_)*B_BUF_U32 + pcp*B_K2STR + (r_)*B_ROWSTR + 2 + ppx; \
        ((uint2*)d_)[0] = make_uint2(packh2(va_.x*s0_, vb_.x*s1_), \
                                     packh2(va_.y*s0_, vb_.y*s1_)); \
        ((uint2*)(d_+2))[0] = make_uint2(packh2(va_.z*s0_, vb_.z*s1_), \
                                         packh2(va_.w*s0_, vb_.w*s1_)); \
    } while (0)

#define BULKA(c_) do { \
        int cc_ = (c_)/9, k_ = (c_) - cc_*9; \
        int sl_ = (c_) % 6; \
        const uint32_t* src_ = g_Wf + (size_t)((k_*2 + ocsel)*8 + cc_)*A_CHUNK_U32; \
        uint32_t dst_ = base + (uint32_t)(SM_A0 + sl_*A_CHUNK_U32)*4u; \
        uint32_t mb_  = base + (uint32_t)(sl_*8); \
        asm volatile("mbarrier.arrive.expect_tx.shared.b64 _, [%0], %1;" \
            :: "r"(mb_), "r"((uint32_t)A_CHUNK_BYTES) : "memory"); \
        asm volatile("cp.async.bulk.shared::cluster.global.mbarrier::complete_tx::bytes " \
            "[%0], [%1], %2, [%3];" \
            :: "r"(dst_), "l"(src_), "r"((uint32_t)A_CHUNK_BYTES), "r"(mb_) : "memory"); \
    } while (0)

    // initial B fill for cc=0
    {
        float4 t0, t1;
        #pragma unroll
        for (int r = 0; r < 4; r++) { LDGROW(r, 0, t0, t1); STSROW(r, 0, 0, t0, t1); }
    }
    if (tid == 0) { BULKA(0); BULKA(1); BULKA(2); BULKA(3); BULKA(4); BULKA(5); }
    __syncthreads();

    float acc[2][8][4];
    #pragma unroll
    for (int m = 0; m < 2; m++)
        #pragma unroll
        for (int n = 0; n < 8; n++)
            #pragma unroll
            for (int i = 0; i < 4; i++) acc[m][n][i] = 0.f;

    const int aidx = (woc*32 + (lane >> 2))*20 + (lane & 3);
    const int bofk = (lane & 3)*B_K2STR + (lane >> 2);

// slot = image col + 2  ->  input col (xo+dx-1) lives at slot (xo+dx+1)
#define COMPUTE(k_, abuf_, bpar_) do { \
        const int dy_ = (k_)/3, dx_ = (k_) - dy_*3; \
        const uint32_t* A_ = smu + SM_A0 + (abuf_)*A_CHUNK_U32 + aidx; \
        const uint32_t* B_ = smu + SM_B0 + (bpar_)*B_BUF_U32 + (wn + dy_)*B_ROWSTR + dx_ + 1 + bofk; \
        _Pragma("unroll") \
        for (int ks = 0; ks < 2; ks++) { \
            uint32_t a00 = A_[ks*8],        a01 = A_[ks*8 + 160]; \
            uint32_t a02 = A_[ks*8 + 4],    a03 = A_[ks*8 + 164]; \
            uint32_t a10 = A_[ks*8 + 320],  a11 = A_[ks*8 + 480]; \
            uint32_t a12 = A_[ks*8 + 324],  a13 = A_[ks*8 + 484]; \
            const uint32_t* Bk_ = B_ + ks*(8*B_K2STR); \
            _Pragma("unroll") \
            for (int nt = 0; nt < 8; nt++) { \
                uint32_t b0 = Bk_[nt*8]; \
                uint32_t b1 = Bk_[nt*8 + 4*B_K2STR]; \
                MMA_F16(acc[0][nt], a00, a01, a02, a03, b0, b1); \
                MMA_F16(acc[1][nt], a10, a11, a12, a13, b0, b1); \
            } \
        } \
    } while (0)

    float4 ra0, ra1, rb0, rb1;

    #pragma unroll 1
    for (int cc = 0; cc < 8; cc++) {
        const int par = cc & 1;
        const int npar = par ^ 1;
        const int ccn = cc + 1;
        const bool more = (cc < 7);
        const int slotb = 3 * par;         // (9*cc) % 6
        #pragma unroll
        for (int k = 0; k < 9; k++) {
            const int c = cc*9 + k;
            if (more) {
                if (k == 0) LDGROW(0, ccn, ra0, ra1);
                if (k == 1) LDGROW(1, ccn, rb0, rb1);
                if (k == 2) { STSROW(0, ccn, npar, ra0, ra1); LDGROW(2, ccn, ra0, ra1); }
                if (k == 3) { STSROW(1, ccn, npar, rb0, rb1); LDGROW(3, ccn, rb0, rb1); }
                if (k == 4) STSROW(2, ccn, npar, ra0, ra1);
                if (k == 5) STSROW(3, ccn, npar, rb0, rb1);
            }
            int sl = slotb + k; if (sl >= 6) sl -= 6;
            const int p6 = (c / 6) & 1;
            mbar_wait(base + sl*8, p6);
            COMPUTE(k, sl, par);
            if (k == 2 || k == 5 || k == 8) {
                __syncthreads();
                if (tid == 0) {
                    if (c + 4 < 72) BULKA(c + 4);
                    if (c + 5 < 72) BULKA(c + 5);
                    if (c + 6 < 72) BULKA(c + 6);
                }
            }
        }
    }

#undef LDGROW
#undef STSROW
#undef BULKA
#undef COMPUTE

    // ---- epilogue: demod, noise, leaky ReLU ----
    const int y = y0 + wn;
    const int r = lane >> 2, tig = lane & 3;
    #pragma unroll
    for (int m = 0; m < 2; m++) {
        const int ocA = oc0 + woc*32 + m*16 + r;
        const int ocB = ocA + 8;
        const float dA = __ldg(&g_demod[b*CC + ocA]);
        const float dB = __ldg(&g_demod[b*CC + ocB]);
        const float nA = __ldg(&nw[ocA]);
        const float nB = __ldg(&nw[ocB]);
        #pragma unroll
        for (int nt = 0; nt < 8; nt++) {
            const int col = nt*8 + tig*2;
            const float2 nz = *(const float2*)(noise + (size_t)b*HW + y*WW + col);
            float v0 = acc[m][nt][0]*dA + nA*nz.x;
            float v1 = acc[m][nt][1]*dA + nA*nz.y;
            float v2 = acc[m][nt][2]*dB + nB*nz.x;
            float v3 = acc[m][nt][3]*dB + nB*nz.y;
            v0 = v0 > 0.f ? v0 : 0.2f*v0;
            v1 = v1 > 0.f ? v1 : 0.2f*v1;
            v2 = v2 > 0.f ? v2 : 0.2f*v2;
            v3 = v3 > 0.f ? v3 : 0.2f*v3;
            *(float2*)(outp + (size_t)(b*CC + ocA)*HW + y*WW + col) = make_float2(v0, v1);
            *(float2*)(outp + (size_t)(b*CC + ocB)*HW + y*WW + col) = make_float2(v2, v3);
        }
    }
}

// ---------------------------------------------------------------------------
extern "C" void kernel_launch(void* const* d_in, const int* in_sizes, int n_in,
                              void* d_out, int out_size) {
    const float* x   = (const float*)d_in[0];
    const float* w1  = (const float*)d_in[1];
    const float* w2  = (const float*)d_in[2];
    const float* n1  = (const float*)d_in[3];
    const float* n2  = (const float*)d_in[4];
    const float* s1w = (const float*)d_in[5];
    const float* s1b = (const float*)d_in[6];
    const float* c1w = (const float*)d_in[7];
    const float* nw1 = (const float*)d_in[8];
    const float* s2w = (const float*)d_in[9];
    const float* s2b = (const float*)d_in[10];
    const float* c2w = (const float*)d_in[11];
    const float* nw2 = (const float*)d_in[12];
    float* out = (float*)d_out;

    static int configured = 0;
    if (!configured) {
        cudaFuncSetAttribute(k_conv, cudaFuncAttributeMaxDynamicSharedMemorySize, SM_BYTES);
        configured = 1;
    }

    dim3 cgrid(32, 2, BB);
    dim3 sgrid(BB, 4);
    dim3 wgrid(9, 2, 8);

    k_style<<<sgrid, 256>>>(w1, s1w, s1b);
    k_rt   <<<CC, 256>>>(c1w);
    k_wf   <<<wgrid, 256>>>(c1w);
    k_demod<<<sgrid, 256>>>();
    k_conv <<<cgrid, 256, SM_BYTES>>>(x, out, n1, nw1, 1);

    k_style<<<sgrid, 256>>>(w2, s2w, s2b);
    k_rt   <<<CC, 256>>>(c2w);
    k_wf   <<<wgrid, 256>>>(c2w);
    k_demod<<<sgrid, 256>>>();
    k_conv <<<cgrid, 256, SM_BYTES>>>(x, out, n2, nw2, 0);
}

// round 10
// speedup vs baseline: 2.6652x; 1.0870x over previous
#include <cuda_runtime.h>
#include <cuda_fp16.h>
#include <cstdint>

#define BB 16
#define CC 256
#define HH 64
#define WW 64
#define SSD 512
#define HW 4096

// A chunk image (fp16 pairs): [128 oc rows][20 u32 words]; word j = ci pair (2j,2j+1), j<16; 4 pad
#define A_CHUNK_U32   2560
#define A_CHUNK_BYTES 10240
#define N_ABUF 6
#define WF_STAGE (9*2*8*A_CHUNK_U32)

// B buffer (fp16 pairs): [16 k2 words][4 rows][68 slots]; slot = col+2 (0,1,66,67 zero)
#define B_K2STR 280
#define B_ROWSTR 68
#define B_BUF_U32 (16*B_K2STR)

// smem u32 map: [0..96B) 12 mbars (6 full + 6 empty), styles at u32 24
#define SM_STY 24
#define SM_A0  288
#define SM_B0  (288 + N_ABUF*A_CHUNK_U32)   // 15648
#define SM_U32 (SM_B0 + 2*B_BUF_U32)        // 24608
#define SM_BYTES (SM_U32*4)                 // 98432

__device__ float    g_inter[BB*CC*HW];
__device__ float    g_style[2*BB*CC];
__device__ float    g_demod[2*BB*CC];
__device__ float    g_Rt[2*CC*CC];
__device__ uint32_t g_Wf[2*WF_STAGE];

// ---------------- helpers ----------------
__device__ __forceinline__ uint32_t smem_u32(const void* p) {
    uint32_t a;
    asm("{ .reg .u64 t; cvta.to.shared.u64 t, %1; cvt.u32.u64 %0, t; }" : "=r"(a) : "l"(p));
    return a;
}
__device__ __forceinline__ uint32_t packh2(float lo, float hi) {
    __half2 h = __floats2half2_rn(lo, hi);
    return *(uint32_t*)&h;
}
__device__ __forceinline__ void mbar_wait(uint32_t mbar, uint32_t parity) {
    asm volatile(
        "{\n\t.reg .pred P;\n\t"
        "WL_%=:\n\t"
        "mbarrier.try_wait.parity.acquire.cta.shared::cta.b64 P, [%0], %1, 0x989680;\n\t"
        "@P bra.uni WD_%=;\n\t"
        "bra.uni WL_%=;\n\t"
        "WD_%=:\n\t}"
        :: "r"(mbar), "r"(parity) : "memory");
}
#define MBAR_INIT(a,n)  asm volatile("mbarrier.init.shared.b64 [%0], %1;" :: "r"(a), "r"((uint32_t)(n)) : "memory")
#define MBAR_ARRIVE(a)  asm volatile("mbarrier.arrive.release.cta.shared::cta.b64 _, [%0];" :: "r"(a) : "memory")

#define MMA_F16(d, a0,a1,a2,a3, b0,b1) \
    asm volatile("mma.sync.aligned.m16n8k16.row.col.f32.f16.f16.f32 " \
        "{%0,%1,%2,%3}, {%4,%5,%6,%7}, {%8,%9}, {%0,%1,%2,%3};" \
        : "+f"((d)[0]), "+f"((d)[1]), "+f"((d)[2]), "+f"((d)[3]) \
        : "r"(a0), "r"(a1), "r"(a2), "r"(a3), "r"(b0), "r"(b1))

// ---------------- prep kernels (double-wide: blockIdx.z selects stage) ----------------
__global__ void k_style(const float* __restrict__ wvA, const float* __restrict__ swA,
                        const float* __restrict__ sbA,
                        const float* __restrict__ wvB, const float* __restrict__ swB,
                        const float* __restrict__ sbB) {
    const int st = blockIdx.z;
    const float* wv = st ? wvB : wvA;
    const float* sw = st ? swB : swA;
    const float* sb = st ? sbB : sbA;
    __shared__ float s[SSD];
    const int b = blockIdx.x, t = threadIdx.x;
    s[t] = wv[b*SSD + t]; s[t+256] = wv[b*SSD + 256 + t];
    __syncthreads();
    const int ch   = blockIdx.y*64 + (t >> 2);
    const int part = t & 3;
    float acc = 0.f;
    const float* rw = sw + (size_t)ch*SSD + part*128;
    const float* sp = s + part*128;
    #pragma unroll 8
    for (int j = 0; j < 128; j++) acc += sp[j] * rw[j];
    acc += __shfl_xor_sync(0xFFFFFFFF, acc, 1);
    acc += __shfl_xor_sync(0xFFFFFFFF, acc, 2);
    if (part == 0) g_style[st*BB*CC + b*CC + ch] = acc * 0.03125f + sb[ch];
}

__global__ void k_rt(const float* __restrict__ wA, const float* __restrict__ wB) {
    const int st = blockIdx.z;
    const float* w = st ? wB : wA;
    const int ci = blockIdx.x, oc = threadIdx.x;
    const float* src = w + (oc*CC + ci)*9;
    float s2 = 0.f;
    #pragma unroll
    for (int k = 0; k < 9; k++) { float v = src[k]; s2 += v*v; }
    g_Rt[st*CC*CC + ci*CC + oc] = s2;
}

__global__ void k_wf(const float* __restrict__ wA, const float* __restrict__ wB) {
    const int k = blockIdx.x, oh = blockIdx.y;
    const int cc = blockIdx.z & 7, st = blockIdx.z >> 3;
    const float* w = st ? wB : wA;
    uint32_t* dst = g_Wf + (size_t)st*WF_STAGE + (size_t)((k*2 + oh)*8 + cc)*A_CHUNK_U32;
    for (int f = threadIdx.x; f < A_CHUNK_U32; f += 256) {
        const int row = f / 20;
        const int j   = f - row*20;
        uint32_t v = 0;
        if (j < 16) {
            const size_t rb = (size_t)((oh*128 + row)*CC + cc*32 + 2*j)*9 + k;
            v = packh2(w[rb], w[rb + 9]);
        }
        dst[f] = v;
    }
}

__global__ void k_demod() {
    const int st = blockIdx.z;
    __shared__ float st2[CC];
    const int b = blockIdx.x, t = threadIdx.x;
    float s = g_style[st*BB*CC + b*CC + t];
    st2[t] = s*s;
    __syncthreads();
    const int ch   = blockIdx.y*64 + (t >> 2);
    const int part = t & 3;
    float acc = 0.f;
    const float* rt = g_Rt + st*CC*CC;
    #pragma unroll 8
    for (int i = 0; i < 64; i++) acc += st2[part*64 + i] * rt[(part*64 + i)*CC + ch];
    acc += __shfl_xor_sync(0xFFFFFFFF, acc, 1);
    acc += __shfl_xor_sync(0xFFFFFFFF, acc, 2);
    if (part == 0) g_demod[st*BB*CC + b*CC + ch] = rsqrtf(acc + 1e-8f);
}

// ---------------- fp16 mma.sync implicit-GEMM conv ----------------
// CTA: M=128 oc x N=128 px. 8 warps. K = 2304 in 72 chunks (2 x m16n8k16).
// A: 6-slot cp.async.bulk ring; full-mbars (tx) + empty-mbars (8 warp arrivals);
// warp0 refills slot c%6 with chunk c+6 each chunk. One __syncthreads per cc
// (B buffer parity swap). B: 4 input rows per cc, double-buffered.
__global__ __launch_bounds__(256, 2)
void k_conv(const float* __restrict__ xg, float* __restrict__ outg,
            const float* __restrict__ noise, const float* __restrict__ nw,
            int st) {
    extern __shared__ uint32_t smu[];
    float* smf = (float*)smu;
    const uint32_t base = smem_u32(smu);

    const float* xin  = (st == 0) ? xg : g_inter;
    float*       outp = (st == 0) ? g_inter : outg;

    const int tid = threadIdx.x, wid = tid >> 5, lane = tid & 31;
    const int woc = wid & 3;
    const int wn  = wid >> 2;
    const int y0  = blockIdx.x * 2;
    const int ocsel = blockIdx.y;
    const int oc0 = ocsel * 128;
    const int b   = blockIdx.z;

    const int pcp = tid >> 4;          // ci pair 0..15
    const int ppx = (tid & 15) * 4;    // px 0..60

    for (int i = tid; i < 2*B_BUF_U32; i += 256) smu[SM_B0 + i] = 0;
    smf[SM_STY + tid] = g_style[st*BB*CC + b*CC + tid];
    if (tid == 0) {
        #pragma unroll
        for (int s = 0; s < 6; s++) {
            MBAR_INIT(base + s*8, 1);        // full[s] (tx-based)
            MBAR_INIT(base + 48 + s*8, 8);   // empty[s] (8 warp arrivals)
        }
    }
    __syncthreads();

#define LDGROW(r_, ccn_, va_, vb_) do { \
        int gy_ = y0 - 1 + (r_); \
        if ((unsigned)gy_ < 64u) { \
            const float* p_ = xin + (size_t)((b*CC + (ccn_)*32 + 2*pcp))*HW + gy_*WW + ppx; \
            va_ = *(const float4*)p_; \
            vb_ = *(const float4*)(p_ + HW); \
        } else { \
            va_ = make_float4(0.f,0.f,0.f,0.f); vb_ = make_float4(0.f,0.f,0.f,0.f); \
        } \
    } while (0)

#define STSROW(r_, ccn_, par_, va_, vb_) do { \
        float s0_ = smf[SM_STY + (ccn_)*32 + 2*pcp]; \
        float s1_ = smf[SM_STY + (ccn_)*32 + 2*pcp + 1]; \
        uint32_t* d_ = smu + SM_B0 + (par_)*B_BUF_U32 + pcp*B_K2STR + (r_)*B_ROWSTR + 2 + ppx; \
        ((uint2*)d_)[0] = make_uint2(packh2(va_.x*s0_, vb_.x*s1_), \
                                     packh2(va_.y*s0_, vb_.y*s1_)); \
        ((uint2*)(d_+2))[0] = make_uint2(packh2(va_.z*s0_, vb_.z*s1_), \
                                         packh2(va_.w*s0_, vb_.w*s1_)); \
    } while (0)

#define BULKA(c_, sl_) do { \
        int cc_ = (c_)/9, k_ = (c_) - cc_*9; \
        const uint32_t* src_ = g_Wf + (size_t)st*WF_STAGE + \
            (size_t)((k_*2 + ocsel)*8 + cc_)*A_CHUNK_U32; \
        uint32_t dst_ = base + (uint32_t)(SM_A0 + (sl_)*A_CHUNK_U32)*4u; \
        uint32_t mb_  = base + (uint32_t)((sl_)*8); \
        asm volatile("mbarrier.arrive.expect_tx.shared.b64 _, [%0], %1;" \
            :: "r"(mb_), "r"((uint32_t)A_CHUNK_BYTES) : "memory"); \
        asm volatile("cp.async.bulk.shared::cluster.global.mbarrier::complete_tx::bytes " \
            "[%0], [%1], %2, [%3];" \
            :: "r"(dst_), "l"(src_), "r"((uint32_t)A_CHUNK_BYTES), "r"(mb_) : "memory"); \
    } while (0)

    // initial B fill for cc=0
    {
        float4 t0, t1;
        #pragma unroll
        for (int r = 0; r < 4; r++) { LDGROW(r, 0, t0, t1); STSROW(r, 0, 0, t0, t1); }
    }
    if (tid == 0) {
        BULKA(0,0); BULKA(1,1); BULKA(2,2); BULKA(3,3); BULKA(4,4); BULKA(5,5);
    }
    __syncthreads();

    float acc[2][8][4];
    #pragma unroll
    for (int m = 0; m < 2; m++)
        #pragma unroll
        for (int n = 0; n < 8; n++)
            #pragma unroll
            for (int i = 0; i < 4; i++) acc[m][n][i] = 0.f;

    const int aidx = (woc*32 + (lane >> 2))*20 + (lane & 3);
    const int bofk = (lane & 3)*B_K2STR + (lane >> 2);

#define COMPUTE(k_, abuf_, bpar_) do { \
        const int dy_ = (k_)/3, dx_ = (k_) - dy_*3; \
        const uint32_t* A_ = smu + SM_A0 + (abuf_)*A_CHUNK_U32 + aidx; \
        const uint32_t* B_ = smu + SM_B0 + (bpar_)*B_BUF_U32 + (wn + dy_)*B_ROWSTR + dx_ + 1 + bofk; \
        _Pragma("unroll") \
        for (int ks = 0; ks < 2; ks++) { \
            uint32_t a00 = A_[ks*8],        a01 = A_[ks*8 + 160]; \
            uint32_t a02 = A_[ks*8 + 4],    a03 = A_[ks*8 + 164]; \
            uint32_t a10 = A_[ks*8 + 320],  a11 = A_[ks*8 + 480]; \
            uint32_t a12 = A_[ks*8 + 324],  a13 = A_[ks*8 + 484]; \
            const uint32_t* Bk_ = B_ + ks*(8*B_K2STR); \
            _Pragma("unroll") \
            for (int nt = 0; nt < 8; nt++) { \
                uint32_t b0 = Bk_[nt*8]; \
                uint32_t b1 = Bk_[nt*8 + 4*B_K2STR]; \
                MMA_F16(acc[0][nt], a00, a01, a02, a03, b0, b1); \
                MMA_F16(acc[1][nt], a10, a11, a12, a13, b0, b1); \
            } \
        } \
    } while (0)

    float4 ra0, ra1, rb0, rb1;

    #pragma unroll 1
    for (int cc = 0; cc < 8; cc++) {
        const int par = cc & 1;
        const int npar = par ^ 1;
        const int ccn = cc + 1;
        const bool more = (cc < 7);
        const int slotb = 3 * par;
        #pragma unroll
        for (int k = 0; k < 9; k++) {
            const int c = cc*9 + k;
            if (more) {
                if (k == 0) LDGROW(0, ccn, ra0, ra1);
                if (k == 1) LDGROW(1, ccn, rb0, rb1);
                if (k == 2) { __syncthreads();  // B parity swap: all warps past cc*9-1
                              STSROW(0, ccn, npar, ra0, ra1); LDGROW(2, ccn, ra0, ra1); }
                if (k == 3) { STSROW(1, ccn, npar, rb0, rb1); LDGROW(3, ccn, rb0, rb1); }
                if (k == 4) STSROW(2, ccn, npar, ra0, ra1);
                if (k == 5) STSROW(3, ccn, npar, rb0, rb1);
            }
            int sl = slotb + k; if (sl >= 6) sl -= 6;
            const int p6 = (c / 6) & 1;
            mbar_wait(base + sl*8, p6);
            COMPUTE(k, sl, par);
            if (lane == 0) MBAR_ARRIVE(base + 48 + sl*8);
            if (tid == 0 && c + 6 < 72) {
                mbar_wait(base + 48 + sl*8, p6);   // all 8 warps done with slot
                BULKA(c + 6, sl);
            }
        }
    }

#undef LDGROW
#undef STSROW
#undef BULKA
#undef COMPUTE

    // ---- epilogue: demod, noise, leaky ReLU ----
    const int y = y0 + wn;
    const int r = lane >> 2, tig = lane & 3;
    const float* dmp = g_demod + st*BB*CC;
    #pragma unroll
    for (int m = 0; m < 2; m++) {
        const int ocA = oc0 + woc*32 + m*16 + r;
        const int ocB = ocA + 8;
        const float dA = __ldg(&dmp[b*CC + ocA]);
        const float dB = __ldg(&dmp[b*CC + ocB]);
        const float nA = __ldg(&nw[ocA]);
        const float nB = __ldg(&nw[ocB]);
        #pragma unroll
        for (int nt = 0; nt < 8; nt++) {
            const int col = nt*8 + tig*2;
            const float2 nz = *(const float2*)(noise + (size_t)b*HW + y*WW + col);
            float v0 = acc[m][nt][0]*dA + nA*nz.x;
            float v1 = acc[m][nt][1]*dA + nA*nz.y;
            float v2 = acc[m][nt][2]*dB + nB*nz.x;
            float v3 = acc[m][nt][3]*dB + nB*nz.y;
            v0 = v0 > 0.f ? v0 : 0.2f*v0;
            v1 = v1 > 0.f ? v1 : 0.2f*v1;
            v2 = v2 > 0.f ? v2 : 0.2f*v2;
            v3 = v3 > 0.f ? v3 : 0.2f*v3;
            *(float2*)(outp + (size_t)(b*CC + ocA)*HW + y*WW + col) = make_float2(v0, v1);
            *(float2*)(outp + (size_t)(b*CC + ocB)*HW + y*WW + col) = make_float2(v2, v3);
        }
    }
}

// ---------------------------------------------------------------------------
extern "C" void kernel_launch(void* const* d_in, const int* in_sizes, int n_in,
                              void* d_out, int out_size) {
    const float* x   = (const float*)d_in[0];
    const float* w1  = (const float*)d_in[1];
    const float* w2  = (const float*)d_in[2];
    const float* n1  = (const float*)d_in[3];
    const float* n2  = (const float*)d_in[4];
    const float* s1w = (const float*)d_in[5];
    const float* s1b = (const float*)d_in[6];
    const float* c1w = (const float*)d_in[7];
    const float* nw1 = (const float*)d_in[8];
    const float* s2w = (const float*)d_in[9];
    const float* s2b = (const float*)d_in[10];
    const float* c2w = (const float*)d_in[11];
    const float* nw2 = (const float*)d_in[12];
    float* out = (float*)d_out;

    static int configured = 0;
    if (!configured) {
        cudaFuncSetAttribute(k_conv, cudaFuncAttributeMaxDynamicSharedMemorySize, SM_BYTES);
        configured = 1;
    }

    dim3 cgrid(32, 2, BB);
    dim3 sgrid(BB, 4, 2);        // both stages
    dim3 rgrid(CC, 1, 2);
    dim3 wgrid(9, 2, 16);        // z = cc | (st<<3)

    // all prep (both stages) up front — 4 launches instead of 8
    k_style<<<sgrid, 256>>>(w1, s1w, s1b, w2, s2w, s2b);
    k_rt   <<<rgrid, 256>>>(c1w, c2w);
    k_wf   <<<wgrid, 256>>>(c1w, c2w);
    k_demod<<<sgrid, 256>>>();

    k_conv <<<cgrid, 256, SM_BYTES>>>(x, out, n1, nw1, 0);
    k_conv <<<cgrid, 256, SM_BYTES>>>(x, out, n2, nw2, 1);
}